// round 5
// baseline (speedup 1.0000x reference)
#include <cuda_runtime.h>
#include <cstdint>
#include <cstddef>

// Problem constants
constexpr int B_  = 64;
constexpr int L_  = 1024;
constexpr int DK_ = 64;
constexpr int P_  = 2047;          // 2*L-1
constexpr float INV_TEMPER = 0.125f;   // 1/sqrt(64)

// Tiling
constexpr int TILE_L    = 16;      // l-rows per CTA
constexpr int MT        = 256;     // m-tile width for GEMM phases
constexpr int SG_STRIDE = 1040;    // G row stride (needs 0..1038)
constexpr int SL_STRIDE = 1028;    // logits row stride (1024 + pad, 16B aligned)
constexpr int ST_STRIDE = 68;      // staging row stride (64 + pad, 16B aligned)

constexpr int SMEM_FLOATS = TILE_L*64*2            // sQ, sQr
                          + TILE_L*SG_STRIDE       // sG
                          + TILE_L*SL_STRIDE       // sL
                          + MT*ST_STRIDE;          // sST (K / pos / V staging)
constexpr int SMEM_BYTES = SMEM_FLOATS * 4;        // 210,176 B

// 1 => mask elements are 4 bytes wide (int32 or float32; nonzero == masked)
// 0 => mask elements are 1 byte wide (uint8 bool)
__device__ int g_mask_w4;

__global__ void detect_mask_kernel(const unsigned char* __restrict__ m)
{
    __shared__ int s_w1, s_f32;
    if (threadIdx.x == 0) { s_w1 = 0; s_f32 = 0; }
    __syncthreads();
    for (int i = threadIdx.x; i < 65536; i += blockDim.x) {
        const unsigned char bb = m[i];
        if (bb > 1) s_f32 = 1;                       // float 1.0f bytes (0x80/0x3f)
        else if (bb == 1 && (i & 3) != 0) s_w1 = 1;  // only possible for 1-byte bools
    }
    __syncthreads();
    if (threadIdx.x == 0) g_mask_w4 = (s_f32 || !s_w1) ? 1 : 0;
}

__global__ void __launch_bounds__(256, 1)
attn_fused_kernel(const float* __restrict__ gq, const float* __restrict__ gk,
                  const float* __restrict__ gv, const float* __restrict__ gpos,
                  const void* __restrict__ gmask,
                  float* __restrict__ gout, float* __restrict__ gattn)
{
    extern __shared__ float smem[];
    float* sQ  = smem;                           // [16][64]
    float* sQr = sQ  + TILE_L*64;                // [16][64]   q rows (L-1-l)
    float* sG  = sQr + TILE_L*64;                // [16][1040] bias band
    float* sL  = sG  + TILE_L*SG_STRIDE;         // [16][1028] logits -> probs
    float* sST = sL  + TILE_L*SL_STRIDE;         // [256][68]  staging

    const int b   = blockIdx.y;
    const int l0  = blockIdx.x * TILE_L;
    const int tid = threadIdx.x;
    const int mask_w4 = g_mask_w4;               // uniform branch selector
    const float NEG_INF = __int_as_float(0xff800000);

    // ---------- Phase 0: load Q rows and reversed Q rows ----------
    {
        const int r  = tid >> 4;            // 0..15
        const int dc = (tid & 15) * 4;      // 0..60
        *(float4*)(sQ  + r*64 + dc) =
            *(const float4*)(gq + ((size_t)b*L_ + (l0 + r))*DK_ + dc);
        *(float4*)(sQr + r*64 + dc) =
            *(const float4*)(gq + ((size_t)b*L_ + (L_ - 1 - (l0 + r)))*DK_ + dc);
    }
    __syncthreads();

    const int lg = tid >> 6;    // 0..3  (l-group: 4 rows each)
    const int mg = tid & 63;    // 0..63 (m-group: 4 cols each)

    // ---------- Phase 1: G[l][s] = qrev[l] . pos[l0+s], s in [0,1039) ----------
    for (int st = 0; st < 5; ++st) {
        {   // stage 256 pos rows
            const int sglob = l0 + st*MT + tid;
            float* dst = sST + tid*ST_STRIDE;
            if (sglob < P_) {
                const float* src = gpos + ((size_t)b*P_ + sglob)*DK_;
                #pragma unroll
                for (int dc = 0; dc < 64; dc += 4)
                    *(float4*)(dst + dc) = *(const float4*)(src + dc);
            } else {
                #pragma unroll
                for (int dc = 0; dc < 64; dc += 4)
                    *(float4*)(dst + dc) = make_float4(0.f, 0.f, 0.f, 0.f);
            }
        }
        __syncthreads();

        float acc[4][4];
        #pragma unroll
        for (int i = 0; i < 4; ++i)
            #pragma unroll
            for (int j = 0; j < 4; ++j) acc[i][j] = 0.f;

        #pragma unroll 8
        for (int dc = 0; dc < 64; dc += 4) {
            float4 av[4], kv[4];
            #pragma unroll
            for (int i = 0; i < 4; ++i)
                av[i] = *(const float4*)(sQr + (lg*4 + i)*64 + dc);
            #pragma unroll
            for (int j = 0; j < 4; ++j)
                kv[j] = *(const float4*)(sST + ((size_t)(mg*4 + j))*ST_STRIDE + dc);
            #pragma unroll
            for (int i = 0; i < 4; ++i)
                #pragma unroll
                for (int j = 0; j < 4; ++j)
                    acc[i][j] += av[i].x*kv[j].x + av[i].y*kv[j].y
                               + av[i].z*kv[j].z + av[i].w*kv[j].w;
        }

        const int sbase = st*MT + mg*4;
        if (sbase < SG_STRIDE) {
            #pragma unroll
            for (int i = 0; i < 4; ++i)
                *(float4*)(sG + (lg*4 + i)*SG_STRIDE + sbase) =
                    make_float4(acc[i][0], acc[i][1], acc[i][2], acc[i][3]);
        }
        __syncthreads();
    }

    // ---------- Phase 2: logits = (Q.K^T + shifted G) * invT, masked ----------
    for (int mt = 0; mt < 4; ++mt) {
        {   // stage 256 K rows
            const int m = mt*MT + tid;
            const float* src = gk + ((size_t)b*L_ + m)*DK_;
            float* dst = sST + tid*ST_STRIDE;
            #pragma unroll
            for (int dc = 0; dc < 64; dc += 4)
                *(float4*)(dst + dc) = *(const float4*)(src + dc);
        }
        __syncthreads();

        float acc[4][4];
        #pragma unroll
        for (int i = 0; i < 4; ++i)
            #pragma unroll
            for (int j = 0; j < 4; ++j) acc[i][j] = 0.f;

        #pragma unroll 8
        for (int dc = 0; dc < 64; dc += 4) {
            float4 av[4], kv[4];
            #pragma unroll
            for (int i = 0; i < 4; ++i)
                av[i] = *(const float4*)(sQ + (lg*4 + i)*64 + dc);
            #pragma unroll
            for (int j = 0; j < 4; ++j)
                kv[j] = *(const float4*)(sST + ((size_t)(mg*4 + j))*ST_STRIDE + dc);
            #pragma unroll
            for (int i = 0; i < 4; ++i)
                #pragma unroll
                for (int j = 0; j < 4; ++j)
                    acc[i][j] += av[i].x*kv[j].x + av[i].y*kv[j].y
                               + av[i].z*kv[j].z + av[i].w*kv[j].w;
        }

        const int mbase = mt*MT + mg*4;
        #pragma unroll
        for (int i = 0; i < 4; ++i) {
            const int ll    = lg*4 + i;
            const int lglob = l0 + ll;
            const size_t midx = ((size_t)b*L_ + lglob)*L_ + mbase;  // element index
            bool m0, m1, m2, m3;
            if (mask_w4) {
                const int4 mk = *(const int4*)((const int*)gmask + midx);
                m0 = mk.x != 0; m1 = mk.y != 0; m2 = mk.z != 0; m3 = mk.w != 0;
            } else {
                const uchar4 mk = *(const uchar4*)((const unsigned char*)gmask + midx);
                m0 = mk.x != 0; m1 = mk.y != 0; m2 = mk.z != 0; m3 = mk.w != 0;
            }
            const float* gr = sG + ll*SG_STRIDE + ll + mbase;
            float4 r;
            r.x = m0 ? NEG_INF : (acc[i][0] + gr[0]) * INV_TEMPER;
            r.y = m1 ? NEG_INF : (acc[i][1] + gr[1]) * INV_TEMPER;
            r.z = m2 ? NEG_INF : (acc[i][2] + gr[2]) * INV_TEMPER;
            r.w = m3 ? NEG_INF : (acc[i][3] + gr[3]) * INV_TEMPER;
            *(float4*)(sL + ll*SL_STRIDE + mbase) = r;
        }
        __syncthreads();
    }

    // ---------- Phase 3: softmax (16 lanes per row) + attn writeback ----------
    const int row = tid >> 4;            // 0..15
    const int tc4 = (tid & 15) * 4;
    float* rowp = sL + row*SL_STRIDE;

    float mx = NEG_INF;
    #pragma unroll
    for (int j = 0; j < 16; ++j) {
        float4 vv = *(const float4*)(rowp + j*64 + tc4);
        mx = fmaxf(mx, fmaxf(fmaxf(vv.x, vv.y), fmaxf(vv.z, vv.w)));
    }
    #pragma unroll
    for (int o = 8; o; o >>= 1) mx = fmaxf(mx, __shfl_xor_sync(0xffffffffu, mx, o));

    float sum = 0.f;
    #pragma unroll
    for (int j = 0; j < 16; ++j) {
        float4 vv = *(float4*)(rowp + j*64 + tc4);
        vv.x = __expf(vv.x - mx);
        vv.y = __expf(vv.y - mx);
        vv.z = __expf(vv.z - mx);
        vv.w = __expf(vv.w - mx);
        sum += (vv.x + vv.y) + (vv.z + vv.w);
        *(float4*)(rowp + j*64 + tc4) = vv;
    }
    #pragma unroll
    for (int o = 8; o; o >>= 1) sum += __shfl_xor_sync(0xffffffffu, sum, o);
    const float inv = 1.f / sum;

    {
        float* arow = gattn + ((size_t)b*L_ + (l0 + row))*L_;
        #pragma unroll
        for (int j = 0; j < 16; ++j) {
            float4 vv = *(const float4*)(rowp + j*64 + tc4);
            vv.x *= inv; vv.y *= inv; vv.z *= inv; vv.w *= inv;
            *(float4*)(arow + j*64 + tc4) = vv;
        }
    }
    __syncthreads();

    // ---------- Phase 4: output = (P @ V) * inv ----------
    const int dc4 = (tid & 15) * 4;
    const int rq  = (tid >> 4) & 3;
    const int mq  = tid >> 6;

    float4 accp[4];
    #pragma unroll
    for (int i = 0; i < 4; ++i) accp[i] = make_float4(0.f, 0.f, 0.f, 0.f);

    for (int mt = 0; mt < 4; ++mt) {
        {   // stage 256 V rows
            const int m = mt*MT + tid;
            const float* src = gv + ((size_t)b*L_ + m)*DK_;
            float* dst = sST + tid*ST_STRIDE;
            #pragma unroll
            for (int dc = 0; dc < 64; dc += 4)
                *(float4*)(dst + dc) = *(const float4*)(src + dc);
        }
        __syncthreads();

        #pragma unroll 4
        for (int mm = 0; mm < 64; ++mm) {
            const int m = mq*64 + mm;
            const float4 v4 = *(const float4*)(sST + (size_t)m*ST_STRIDE + dc4);
            #pragma unroll
            for (int i = 0; i < 4; ++i) {
                const float p = sL[(rq*4 + i)*SL_STRIDE + mt*MT + m];
                accp[i].x += p*v4.x; accp[i].y += p*v4.y;
                accp[i].z += p*v4.z; accp[i].w += p*v4.w;
            }
        }
        __syncthreads();
    }

    // reduce the 4 m-quads through smem (sST is free now)
    #pragma unroll
    for (int i = 0; i < 4; ++i)
        *(float4*)(sST + (size_t)(mq*256 + (rq*4 + i)*16 + (tid & 15))*4) = accp[i];
    __syncthreads();

    {
        const int orow = tid >> 4;       // same row mapping as phase 3 -> inv valid
        float4 s0 = *(const float4*)(sST + (size_t)(0*256 + orow*16 + (tid & 15))*4);
        float4 s1 = *(const float4*)(sST + (size_t)(1*256 + orow*16 + (tid & 15))*4);
        float4 s2 = *(const float4*)(sST + (size_t)(2*256 + orow*16 + (tid & 15))*4);
        float4 s3 = *(const float4*)(sST + (size_t)(3*256 + orow*16 + (tid & 15))*4);
        float4 o;
        o.x = ((s0.x + s1.x) + (s2.x + s3.x)) * inv;
        o.y = ((s0.y + s1.y) + (s2.y + s3.y)) * inv;
        o.z = ((s0.z + s1.z) + (s2.z + s3.z)) * inv;
        o.w = ((s0.w + s1.w) + (s2.w + s3.w)) * inv;
        *(float4*)(gout + ((size_t)b*L_ + (l0 + orow))*DK_ + dc4) = o;
    }
}

extern "C" void kernel_launch(void* const* d_in, const int* in_sizes, int n_in,
                              void* d_out, int out_size)
{
    // Identify inputs robustly by element count:
    //   q,k,v : B*L*DK   = 4,194,304  (in encounter order)
    //   pos   : B*P*DK   = 8,384,512
    //   mask  : B*L*L    = 67,108,864
    const float* q   = nullptr;
    const float* k   = nullptr;
    const float* v   = nullptr;
    const float* pos = nullptr;
    const void*  mask = nullptr;
    int qkv_seen = 0;
    for (int i = 0; i < n_in; ++i) {
        const long long sz = in_sizes[i];
        if (sz == (long long)B_ * P_ * DK_) {
            pos = (const float*)d_in[i];
        } else if (sz == (long long)B_ * L_ * L_) {
            mask = d_in[i];
        } else if (sz == (long long)B_ * L_ * DK_) {
            if      (qkv_seen == 0) q = (const float*)d_in[i];
            else if (qkv_seen == 1) k = (const float*)d_in[i];
            else                    v = (const float*)d_in[i];
            ++qkv_seen;
        }
    }

    float* out  = (float*)d_out;                       // (B, L, DK) first
    float* attn = out + (size_t)B_ * L_ * DK_;         // (B, L, L) second

    cudaFuncSetAttribute(attn_fused_kernel,
                         cudaFuncAttributeMaxDynamicSharedMemorySize, SMEM_BYTES);

    detect_mask_kernel<<<1, 256>>>((const unsigned char*)mask);

    dim3 grid(L_ / TILE_L, B_);
    attn_fused_kernel<<<grid, 256, SMEM_BYTES>>>(q, k, v, pos, mask, out, attn);
}

// round 7
// speedup vs baseline: 2.4540x; 2.4540x over previous
#include <cuda_runtime.h>
#include <cstdint>
#include <cstddef>

constexpr int B_  = 64;
constexpr int L_  = 1024;
constexpr int DK_ = 64;
constexpr int P_  = 2047;              // 2*L-1
constexpr float INV_TEMPER = 0.125f;   // 1/sqrt(64)

constexpr int TILE_L    = 16;
constexpr int NTHREADS  = 512;
constexpr int SL_STRIDE = 1028;        // 1024 + pad (16B-aligned rows)
constexpr int CK_STRIDE = 20;          // 16 floats + 4 pad (80B, 16B-aligned)
constexpr int CK_ROWS   = 1040;
constexpr int NCHUNK    = 4;           // 4 dc-chunks of 16 floats = DK 64

constexpr int SMEM_FLOATS = TILE_L*64*2            // sQ, sQr
                          + TILE_L*SL_STRIDE       // sL (bias -> logits -> probs)
                          + CK_ROWS*CK_STRIDE      // sCK (staging / PV partials)
                          + 16;                    // sInv
constexpr int SMEM_BYTES = SMEM_FLOATS * 4;        // 157,248 B

// 1 => mask elements 4 bytes wide (int32/float32, nonzero == masked); 0 => 1-byte bool
__device__ int g_mask_w4;

__global__ void detect_mask_kernel(const unsigned char* __restrict__ m)
{
    __shared__ int s_w1, s_f32;
    if (threadIdx.x == 0) { s_w1 = 0; s_f32 = 0; }
    __syncthreads();
    for (int i = threadIdx.x; i < 65536; i += blockDim.x) {
        const unsigned char bb = m[i];
        if (bb > 1) s_f32 = 1;
        else if (bb == 1 && (i & 3) != 0) s_w1 = 1;
    }
    __syncthreads();
    if (threadIdx.x == 0) g_mask_w4 = (s_f32 || !s_w1) ? 1 : 0;
}

__device__ __forceinline__ float dot4(float4 a, float4 b) {
    return a.x*b.x + a.y*b.y + a.z*b.z + a.w*b.w;
}

__global__ void __launch_bounds__(NTHREADS, 1)
attn_fused_kernel(const float* __restrict__ gq, const float* __restrict__ gk,
                  const float* __restrict__ gv, const float* __restrict__ gpos,
                  const void* __restrict__ gmask,
                  float* __restrict__ gout, float* __restrict__ gattn)
{
    extern __shared__ float smem[];
    float* sQ   = smem;                          // [16][64]
    float* sQr  = sQ  + TILE_L*64;               // [16][64]
    float* sL   = sQr + TILE_L*64;               // [16][1028]
    float* sCK  = sL  + TILE_L*SL_STRIDE;        // [1040][20] staging
    float* sInv = sCK + CK_ROWS*CK_STRIDE;       // [16]

    const int b   = blockIdx.y;
    const int l0  = blockIdx.x * TILE_L;
    const int tid = threadIdx.x;
    const int mask_w4 = g_mask_w4;
    const float NEG_INF = __int_as_float(0xff800000);

    // ---------- Phase 0: load Q and reversed-Q rows ----------
    if (tid < 512) {
        const int h = tid & 255;
        const int r = h >> 4, q4 = (h & 15) * 4;
        if (tid < 256)
            *(float4*)(sQ + r*64 + q4) =
                *(const float4*)(gq + ((size_t)b*L_ + (l0 + r))*DK_ + q4);
        else
            *(float4*)(sQr + r*64 + q4) =
                *(const float4*)(gq + ((size_t)b*L_ + (L_ - 1 - (l0 + r)))*DK_ + q4);
    }
    __syncthreads();

    // staging f4-index mapping: j = tid + i*512 -> row=j>>2, q=j&3
    const int pfn = (CK_ROWS*4 - tid + (NTHREADS-1)) / NTHREADS;  // 8 or 9
    float4 pf[9];

    const int r0 = tid, r1 = tid + 512;
    float acc[16][2];

    // ================== Phase 1: bias GEMM  G[l][s] = qrev[l].pos[l0+s] ==================
    {
        const float* src = gpos + ((size_t)b*P_ + l0)*DK_;   // row s -> src + s*64
        const int rowLim = 1039;                              // s=1039 zero (l0+1039 may be OOB)

        #pragma unroll
        for (int i = 0; i < 16; ++i) { acc[i][0] = 0.f; acc[i][1] = 0.f; }

        // prefetch chunk 0
        #pragma unroll
        for (int i = 0; i < 9; ++i) {
            if (i < pfn) {
                const int j = tid + i*NTHREADS, row = j >> 2, q = j & 3;
                pf[i] = (row < rowLim)
                    ? *(const float4*)(src + (size_t)row*DK_ + q*4)
                    : make_float4(0.f,0.f,0.f,0.f);
            }
        }

        for (int c = 0; c < NCHUNK; ++c) {
            __syncthreads();   // sCK free
            #pragma unroll
            for (int i = 0; i < 9; ++i) {
                if (i < pfn) {
                    const int j = tid + i*NTHREADS, row = j >> 2, q = j & 3;
                    *(float4*)(sCK + row*CK_STRIDE + q*4) = pf[i];
                }
            }
            __syncthreads();
            if (c < NCHUNK-1) {   // prefetch next chunk (overlaps GEMM below)
                #pragma unroll
                for (int i = 0; i < 9; ++i) {
                    if (i < pfn) {
                        const int j = tid + i*NTHREADS, row = j >> 2, q = j & 3;
                        pf[i] = (row < rowLim)
                            ? *(const float4*)(src + (size_t)row*DK_ + (c+1)*16 + q*4)
                            : make_float4(0.f,0.f,0.f,0.f);
                    }
                }
            }
            #pragma unroll
            for (int s4 = 0; s4 < 4; ++s4) {
                const float4 kv0 = *(const float4*)(sCK + r0*CK_STRIDE + s4*4);
                const float4 kv1 = *(const float4*)(sCK + r1*CK_STRIDE + s4*4);
                const int dc = c*16 + s4*4;
                #pragma unroll
                for (int i = 0; i < 16; ++i) {
                    const float4 a = *(const float4*)(sQr + i*64 + dc);
                    acc[i][0] += dot4(a, kv0);
                    acc[i][1] += dot4(a, kv1);
                }
            }
        }
        __syncthreads();

        // scatter: sL[i][s - i] = G[i][s]   (each (i,m) written exactly once)
        #pragma unroll
        for (int i = 0; i < 16; ++i) {
            const int m0 = r0 - i;
            if (m0 >= 0) sL[i*SL_STRIDE + m0] = acc[i][0];
            const int m1 = r1 - i;
            if (m1 < 1024) sL[i*SL_STRIDE + m1] = acc[i][1];
        }
        __syncthreads();

        // tail cols s = 1024..1038
        if (tid < 240) {   // stage 15 rows x 64 floats
            const int row = tid >> 4, q4 = (tid & 15)*4;
            *(float4*)(sCK + row*68 + q4) =
                *(const float4*)(src + (size_t)(1024 + row)*DK_ + q4);
        }
        __syncthreads();
        if (tid < 15) {
            const int s = 1024 + tid;
            float accT[16];
            #pragma unroll
            for (int i = 0; i < 16; ++i) accT[i] = 0.f;
            #pragma unroll
            for (int q = 0; q < 16; ++q) {
                const float4 kv = *(const float4*)(sCK + tid*68 + q*4);
                #pragma unroll
                for (int i = 0; i < 16; ++i) {
                    const float4 a = *(const float4*)(sQr + i*64 + q*4);
                    accT[i] += dot4(a, kv);
                }
            }
            #pragma unroll
            for (int i = 0; i < 16; ++i) {
                const int m = s - i;
                if (m < 1024) sL[i*SL_STRIDE + m] = accT[i];
            }
        }
        __syncthreads();
    }

    // ================== Phase 2: QK GEMM + bias + mask -> logits in sL ==================
    {
        const float* src = gk + ((size_t)b*L_)*DK_;
        const int rowLim = 1024;

        #pragma unroll
        for (int i = 0; i < 16; ++i) { acc[i][0] = 0.f; acc[i][1] = 0.f; }

        #pragma unroll
        for (int i = 0; i < 9; ++i) {
            if (i < pfn) {
                const int j = tid + i*NTHREADS, row = j >> 2, q = j & 3;
                pf[i] = (row < rowLim)
                    ? *(const float4*)(src + (size_t)row*DK_ + q*4)
                    : make_float4(0.f,0.f,0.f,0.f);
            }
        }

        for (int c = 0; c < NCHUNK; ++c) {
            __syncthreads();
            #pragma unroll
            for (int i = 0; i < 9; ++i) {
                if (i < pfn) {
                    const int j = tid + i*NTHREADS, row = j >> 2, q = j & 3;
                    *(float4*)(sCK + row*CK_STRIDE + q*4) = pf[i];
                }
            }
            __syncthreads();
            if (c < NCHUNK-1) {
                #pragma unroll
                for (int i = 0; i < 9; ++i) {
                    if (i < pfn) {
                        const int j = tid + i*NTHREADS, row = j >> 2, q = j & 3;
                        pf[i] = (row < rowLim)
                            ? *(const float4*)(src + (size_t)row*DK_ + (c+1)*16 + q*4)
                            : make_float4(0.f,0.f,0.f,0.f);
                    }
                }
            }
            #pragma unroll
            for (int s4 = 0; s4 < 4; ++s4) {
                const float4 kv0 = *(const float4*)(sCK + r0*CK_STRIDE + s4*4);
                const float4 kv1 = *(const float4*)(sCK + r1*CK_STRIDE + s4*4);
                const int dc = c*16 + s4*4;
                #pragma unroll
                for (int i = 0; i < 16; ++i) {
                    const float4 a = *(const float4*)(sQ + i*64 + dc);
                    acc[i][0] += dot4(a, kv0);
                    acc[i][1] += dot4(a, kv1);
                }
            }
        }
        __syncthreads();

        // combine with bias (already in sL), apply mask, write logits
        if (mask_w4) {
            const int* mbase = (const int*)gmask + ((size_t)b*L_ + l0)*L_;
            #pragma unroll
            for (int i = 0; i < 16; ++i) {
                const int mk0 = mbase[(size_t)i*L_ + r0];
                const int mk1 = mbase[(size_t)i*L_ + r1];
                float* p0 = sL + i*SL_STRIDE + r0;
                float* p1 = sL + i*SL_STRIDE + r1;
                *p0 = mk0 ? NEG_INF : (acc[i][0] + *p0) * INV_TEMPER;
                *p1 = mk1 ? NEG_INF : (acc[i][1] + *p1) * INV_TEMPER;
            }
        } else {
            const unsigned char* mbase = (const unsigned char*)gmask + ((size_t)b*L_ + l0)*L_;
            #pragma unroll
            for (int i = 0; i < 16; ++i) {
                const unsigned char mk0 = mbase[(size_t)i*L_ + r0];
                const unsigned char mk1 = mbase[(size_t)i*L_ + r1];
                float* p0 = sL + i*SL_STRIDE + r0;
                float* p1 = sL + i*SL_STRIDE + r1;
                *p0 = mk0 ? NEG_INF : (acc[i][0] + *p0) * INV_TEMPER;
                *p1 = mk1 ? NEG_INF : (acc[i][1] + *p1) * INV_TEMPER;
            }
        }
        __syncthreads();
    }

    // ================== Phase 3: softmax (one warp per row) + attn writeback ==========
    {
        const int row  = tid >> 5;     // 16 warps -> 16 rows
        const int lane = tid & 31;
        float* rowp = sL + row*SL_STRIDE;

        float mx = NEG_INF;
        #pragma unroll
        for (int j = 0; j < 8; ++j) {
            const float4 vv = *(const float4*)(rowp + j*128 + lane*4);
            mx = fmaxf(mx, fmaxf(fmaxf(vv.x, vv.y), fmaxf(vv.z, vv.w)));
        }
        #pragma unroll
        for (int o = 16; o; o >>= 1) mx = fmaxf(mx, __shfl_xor_sync(0xffffffffu, mx, o));

        float sum = 0.f;
        #pragma unroll
        for (int j = 0; j < 8; ++j) {
            float4 vv = *(float4*)(rowp + j*128 + lane*4);
            vv.x = __expf(vv.x - mx); vv.y = __expf(vv.y - mx);
            vv.z = __expf(vv.z - mx); vv.w = __expf(vv.w - mx);
            sum += (vv.x + vv.y) + (vv.z + vv.w);
            *(float4*)(rowp + j*128 + lane*4) = vv;   // unnormalized exp kept in sL
        }
        #pragma unroll
        for (int o = 16; o; o >>= 1) sum += __shfl_xor_sync(0xffffffffu, sum, o);
        const float inv = 1.f / sum;
        if (lane == 0) sInv[row] = inv;

        float* arow = gattn + ((size_t)b*L_ + (l0 + row))*L_;
        #pragma unroll
        for (int j = 0; j < 8; ++j) {
            float4 vv = *(const float4*)(rowp + j*128 + lane*4);
            vv.x *= inv; vv.y *= inv; vv.z *= inv; vv.w *= inv;
            *(float4*)(arow + j*128 + lane*4) = vv;
        }
    }
    __syncthreads();

    // ================== Phase 4: output = (exp-probs @ V) * inv =====================
    {
        const int cg = tid & 15;          // d-cols 4cg..4cg+3
        const int rg = (tid >> 4) & 3;    // rows 4rg..4rg+3
        const int ms = tid >> 6;          // 8 m-splits of 128

        float4 accp[4];
        #pragma unroll
        for (int i = 0; i < 4; ++i) accp[i] = make_float4(0.f,0.f,0.f,0.f);

        const float* vbase = gv + ((size_t)b*L_ + ms*128)*DK_ + cg*4;
        const float* pbase = sL + (rg*4)*SL_STRIDE + ms*128;

        #pragma unroll 4
        for (int mm = 0; mm < 128; mm += 2) {
            const float4 v0 = *(const float4*)(vbase + (size_t)mm*DK_);
            const float4 v1 = *(const float4*)(vbase + (size_t)(mm+1)*DK_);
            #pragma unroll
            for (int i = 0; i < 4; ++i) {
                const float2 p = *(const float2*)(pbase + i*SL_STRIDE + mm);
                accp[i].x += p.x*v0.x + p.y*v1.x;
                accp[i].y += p.x*v0.y + p.y*v1.y;
                accp[i].z += p.x*v0.z + p.y*v1.z;
                accp[i].w += p.x*v0.w + p.y*v1.w;
            }
        }
        // partials: sCK[(ms*16 + row)*16 + cg] as float4
        #pragma unroll
        for (int i = 0; i < 4; ++i)
            *(float4*)(sCK + (size_t)((ms*16 + rg*4 + i)*16 + cg)*4) = accp[i];
    }
    __syncthreads();

    if (tid < 256) {
        const int row = tid >> 4, cg = tid & 15;
        float4 s = make_float4(0.f,0.f,0.f,0.f);
        #pragma unroll
        for (int ms = 0; ms < 8; ++ms) {
            const float4 p = *(const float4*)(sCK + (size_t)((ms*16 + row)*16 + cg)*4);
            s.x += p.x; s.y += p.y; s.z += p.z; s.w += p.w;
        }
        const float inv = sInv[row];
        s.x *= inv; s.y *= inv; s.z *= inv; s.w *= inv;
        *(float4*)(gout + ((size_t)b*L_ + (l0 + row))*DK_ + cg*4) = s;
    }
}

extern "C" void kernel_launch(void* const* d_in, const int* in_sizes, int n_in,
                              void* d_out, int out_size)
{
    // Identify inputs by element count; q,k,v in encounter order.
    const float* q   = nullptr;
    const float* k   = nullptr;
    const float* v   = nullptr;
    const float* pos = nullptr;
    const void*  mask = nullptr;
    int qkv_seen = 0;
    for (int i = 0; i < n_in; ++i) {
        const long long sz = in_sizes[i];
        if (sz == (long long)B_ * P_ * DK_) {
            pos = (const float*)d_in[i];
        } else if (sz == (long long)B_ * L_ * L_) {
            mask = d_in[i];
        } else if (sz == (long long)B_ * L_ * DK_) {
            if      (qkv_seen == 0) q = (const float*)d_in[i];
            else if (qkv_seen == 1) k = (const float*)d_in[i];
            else                    v = (const float*)d_in[i];
            ++qkv_seen;
        }
    }

    float* out  = (float*)d_out;                       // (B, L, DK) first
    float* attn = out + (size_t)B_ * L_ * DK_;         // (B, L, L) second

    cudaFuncSetAttribute(attn_fused_kernel,
                         cudaFuncAttributeMaxDynamicSharedMemorySize, SMEM_BYTES);

    detect_mask_kernel<<<1, 256>>>((const unsigned char*)mask);

    dim3 grid(L_ / TILE_L, B_);
    attn_fused_kernel<<<grid, NTHREADS, SMEM_BYTES>>>(q, k, v, pos, mask, out, attn);
}

// round 8
// speedup vs baseline: 2.6065x; 1.0621x over previous
#include <cuda_runtime.h>
#include <cstdint>
#include <cstddef>

constexpr int B_  = 64;
constexpr int L_  = 1024;
constexpr int DK_ = 64;
constexpr int P_  = 2047;              // 2*L-1
constexpr float INV_TEMPER = 0.125f;   // 1/sqrt(64)

constexpr int TILE_L    = 16;
constexpr int NTHREADS  = 512;
constexpr int SL_STRIDE = 1028;        // 1024 + pad (16B-aligned rows)
constexpr int CK_STRIDE = 20;          // 16 floats + 4 pad (80B, 16B-aligned)
constexpr int CK_ROWS   = 1040;
constexpr int NCHUNK    = 4;           // 4 dc-chunks of 16 floats = DK 64

constexpr int SMEM_FLOATS = TILE_L*64*2            // sQ, sQr (direct)
                          + TILE_L*64*2            // sQp, sQrp (row-pair packed)
                          + TILE_L*SL_STRIDE       // sL (bias -> logits -> probs)
                          + CK_ROWS*CK_STRIDE      // sCK (staging / PV partials)
                          + 16;                    // sInv
constexpr int SMEM_BYTES = SMEM_FLOATS * 4;        // 165,440 B

// 1 => mask elements 4 bytes wide (int32/float32, nonzero == masked); 0 => 1-byte bool
__device__ int g_mask_w4;

__global__ void detect_mask_kernel(const unsigned char* __restrict__ m)
{
    __shared__ int s_w1, s_f32;
    if (threadIdx.x == 0) { s_w1 = 0; s_f32 = 0; }
    __syncthreads();
    for (int i = threadIdx.x; i < 65536; i += blockDim.x) {
        const unsigned char bb = m[i];
        if (bb > 1) s_f32 = 1;
        else if (bb == 1 && (i & 3) != 0) s_w1 = 1;
    }
    __syncthreads();
    if (threadIdx.x == 0) g_mask_w4 = (s_f32 || !s_w1) ? 1 : 0;
}

// ---------------- packed f32x2 helpers (sm_103a FFMA2 path) ----------------
__device__ __forceinline__ unsigned long long pack2(float lo, float hi) {
    unsigned long long r;
    asm("mov.b64 %0, {%1, %2};" : "=l"(r) : "f"(lo), "f"(hi));
    return r;
}
__device__ __forceinline__ unsigned long long splat2(float v) {
    unsigned long long r;
    asm("mov.b64 %0, {%1, %1};" : "=l"(r) : "f"(v));
    return r;
}
__device__ __forceinline__ unsigned long long fma2(unsigned long long a,
                                                   unsigned long long b,
                                                   unsigned long long c) {
    unsigned long long d;
    asm("fma.rn.f32x2 %0, %1, %2, %3;" : "=l"(d) : "l"(a), "l"(b), "l"(c));
    return d;
}
__device__ __forceinline__ float2 unpack2(unsigned long long v) {
    float lo, hi;
    asm("mov.b64 {%0, %1}, %2;" : "=f"(lo), "=f"(hi) : "l"(v));
    return make_float2(lo, hi);
}

__device__ __forceinline__ float dot4(float4 a, float4 b) {
    return a.x*b.x + a.y*b.y + a.z*b.z + a.w*b.w;
}

__global__ void __launch_bounds__(NTHREADS, 1)
attn_fused_kernel(const float* __restrict__ gq, const float* __restrict__ gk,
                  const float* __restrict__ gv, const float* __restrict__ gpos,
                  const void* __restrict__ gmask,
                  float* __restrict__ gout, float* __restrict__ gattn)
{
    extern __shared__ float smem[];
    float* sQ   = smem;                          // [16][64]  direct
    float* sQr  = sQ   + TILE_L*64;              // [16][64]  direct
    float* sQp  = sQr  + TILE_L*64;              // [64][8] f32x2 row-pairs of Q
    float* sQrp = sQp  + TILE_L*64;              // [64][8] f32x2 row-pairs of Qr
    float* sL   = sQrp + TILE_L*64;              // [16][1028]
    float* sCK  = sL   + TILE_L*SL_STRIDE;       // [1040][20] staging
    float* sInv = sCK  + CK_ROWS*CK_STRIDE;      // [16]

    const int b   = blockIdx.y;
    const int l0  = blockIdx.x * TILE_L;
    const int tid = threadIdx.x;
    const int mask_w4 = g_mask_w4;
    const float NEG_INF = __int_as_float(0xff800000);

    // ---------- Phase 0: load Q / reversed-Q rows, then build packed copies ----------
    {
        const int h = tid & 255;
        const int r = h >> 4, q4 = (h & 15) * 4;
        if (tid < 256)
            *(float4*)(sQ + r*64 + q4) =
                *(const float4*)(gq + ((size_t)b*L_ + (l0 + r))*DK_ + q4);
        else
            *(float4*)(sQr + r*64 + q4) =
                *(const float4*)(gq + ((size_t)b*L_ + (L_ - 1 - (l0 + r)))*DK_ + q4);
    }
    __syncthreads();
    {
        // packed layout: sQp[(e*8 + p)*2 + (r&1)] = sQ[r][e], p = r>>1
        #pragma unroll
        for (int t = 0; t < 2; ++t) {
            const int j = tid*2 + t;
            const int r = j >> 6, e = j & 63;
            const int di = (e*8 + (r >> 1))*2 + (r & 1);
            sQp[di]  = sQ[r*64 + e];
            sQrp[di] = sQr[r*64 + e];
        }
    }
    __syncthreads();

    // staging f4-index mapping: j = tid + i*512 -> row=j>>2, q=j&3
    const int pfn = (CK_ROWS*4 - tid + (NTHREADS-1)) / NTHREADS;  // 8 or 9
    float4 pf[9];

    const int r0 = tid, r1 = tid + 512;

    // acc2[p][col]: rows (2p, 2p+1) packed, col 0 -> m=r0, col 1 -> m=r1
    unsigned long long acc2[8][2];

    // ======== Phases 1 & 2 share this GEMM skeleton (A = packed Qr or Q) ========
    #pragma unroll 1
    for (int phase = 0; phase < 2; ++phase) {
        const float* ap      = phase == 0 ? sQrp : sQp;
        const float* src     = phase == 0 ? gpos + ((size_t)b*P_ + l0)*DK_
                                          : gk   + ((size_t)b*L_)*DK_;
        const int    rowLim  = phase == 0 ? 1039 : 1024;

        #pragma unroll
        for (int p = 0; p < 8; ++p) { acc2[p][0] = 0ull; acc2[p][1] = 0ull; }

        // prefetch chunk 0
        #pragma unroll
        for (int i = 0; i < 9; ++i) {
            if (i < pfn) {
                const int j = tid + i*NTHREADS, row = j >> 2, q = j & 3;
                pf[i] = (row < rowLim)
                    ? *(const float4*)(src + (size_t)row*DK_ + q*4)
                    : make_float4(0.f,0.f,0.f,0.f);
            }
        }

        for (int c = 0; c < NCHUNK; ++c) {
            __syncthreads();   // sCK free
            #pragma unroll
            for (int i = 0; i < 9; ++i) {
                if (i < pfn) {
                    const int j = tid + i*NTHREADS, row = j >> 2, q = j & 3;
                    *(float4*)(sCK + row*CK_STRIDE + q*4) = pf[i];
                }
            }
            __syncthreads();
            if (c < NCHUNK-1) {   // prefetch next chunk (overlaps GEMM below)
                #pragma unroll
                for (int i = 0; i < 9; ++i) {
                    if (i < pfn) {
                        const int j = tid + i*NTHREADS, row = j >> 2, q = j & 3;
                        pf[i] = (row < rowLim)
                            ? *(const float4*)(src + (size_t)row*DK_ + (c+1)*16 + q*4)
                            : make_float4(0.f,0.f,0.f,0.f);
                    }
                }
            }
            #pragma unroll
            for (int s4 = 0; s4 < 4; ++s4) {
                const float4 kv0 = *(const float4*)(sCK + r0*CK_STRIDE + s4*4);
                const float4 kv1 = *(const float4*)(sCK + r1*CK_STRIDE + s4*4);
                const int dcb = (c*16 + s4*4) * 16;   // float index of packed row-pairs
                #pragma unroll
                for (int e = 0; e < 4; ++e) {
                    const float ke0 = e==0?kv0.x : e==1?kv0.y : e==2?kv0.z : kv0.w;
                    const float ke1 = e==0?kv1.x : e==1?kv1.y : e==2?kv1.z : kv1.w;
                    const unsigned long long k0 = splat2(ke0);
                    const unsigned long long k1 = splat2(ke1);
                    const ulonglong2* a2 = (const ulonglong2*)(ap + dcb + e*16);
                    const ulonglong2 a01 = a2[0], a23 = a2[1], a45 = a2[2], a67 = a2[3];
                    acc2[0][0] = fma2(a01.x, k0, acc2[0][0]);
                    acc2[0][1] = fma2(a01.x, k1, acc2[0][1]);
                    acc2[1][0] = fma2(a01.y, k0, acc2[1][0]);
                    acc2[1][1] = fma2(a01.y, k1, acc2[1][1]);
                    acc2[2][0] = fma2(a23.x, k0, acc2[2][0]);
                    acc2[2][1] = fma2(a23.x, k1, acc2[2][1]);
                    acc2[3][0] = fma2(a23.y, k0, acc2[3][0]);
                    acc2[3][1] = fma2(a23.y, k1, acc2[3][1]);
                    acc2[4][0] = fma2(a45.x, k0, acc2[4][0]);
                    acc2[4][1] = fma2(a45.x, k1, acc2[4][1]);
                    acc2[5][0] = fma2(a45.y, k0, acc2[5][0]);
                    acc2[5][1] = fma2(a45.y, k1, acc2[5][1]);
                    acc2[6][0] = fma2(a67.x, k0, acc2[6][0]);
                    acc2[6][1] = fma2(a67.x, k1, acc2[6][1]);
                    acc2[7][0] = fma2(a67.y, k0, acc2[7][0]);
                    acc2[7][1] = fma2(a67.y, k1, acc2[7][1]);
                }
            }
        }
        __syncthreads();

        if (phase == 0) {
            // scatter bias: sL[i][s - i] = G[i][s]  (each (i,m) written exactly once)
            #pragma unroll
            for (int p = 0; p < 8; ++p) {
                const float2 g0 = unpack2(acc2[p][0]);   // rows 2p, 2p+1 at s=r0
                const float2 g1 = unpack2(acc2[p][1]);   // rows 2p, 2p+1 at s=r1
                const int i0 = 2*p, i1 = 2*p + 1;
                int m;
                m = r0 - i0; if (m >= 0)   sL[i0*SL_STRIDE + m] = g0.x;
                m = r0 - i1; if (m >= 0)   sL[i1*SL_STRIDE + m] = g0.y;
                m = r1 - i0; if (m < 1024) sL[i0*SL_STRIDE + m] = g1.x;
                m = r1 - i1; if (m < 1024) sL[i1*SL_STRIDE + m] = g1.y;
            }
            __syncthreads();

            // tail cols s = 1024..1038
            if (tid < 240) {   // stage 15 rows x 64 floats
                const int row = tid >> 4, q4 = (tid & 15)*4;
                *(float4*)(sCK + row*68 + q4) =
                    *(const float4*)(src + (size_t)(1024 + row)*DK_ + q4);
            }
            __syncthreads();
            if (tid < 15) {
                const int s = 1024 + tid;
                float accT[16];
                #pragma unroll
                for (int i = 0; i < 16; ++i) accT[i] = 0.f;
                #pragma unroll
                for (int q = 0; q < 16; ++q) {
                    const float4 kv = *(const float4*)(sCK + tid*68 + q*4);
                    #pragma unroll
                    for (int i = 0; i < 16; ++i) {
                        const float4 a = *(const float4*)(sQr + i*64 + q*4);
                        accT[i] += dot4(a, kv);
                    }
                }
                #pragma unroll
                for (int i = 0; i < 16; ++i) {
                    const int m = s - i;
                    if (m < 1024) sL[i*SL_STRIDE + m] = accT[i];
                }
            }
            __syncthreads();
        } else {
            // combine with bias (already in sL), apply mask, write logits
            float accv[16][2];
            #pragma unroll
            for (int p = 0; p < 8; ++p) {
                const float2 g0 = unpack2(acc2[p][0]);
                const float2 g1 = unpack2(acc2[p][1]);
                accv[2*p  ][0] = g0.x; accv[2*p+1][0] = g0.y;
                accv[2*p  ][1] = g1.x; accv[2*p+1][1] = g1.y;
            }
            if (mask_w4) {
                const int* mbase = (const int*)gmask + ((size_t)b*L_ + l0)*L_;
                #pragma unroll
                for (int i = 0; i < 16; ++i) {
                    const int mk0 = mbase[(size_t)i*L_ + r0];
                    const int mk1 = mbase[(size_t)i*L_ + r1];
                    float* p0 = sL + i*SL_STRIDE + r0;
                    float* p1 = sL + i*SL_STRIDE + r1;
                    *p0 = mk0 ? NEG_INF : (accv[i][0] + *p0) * INV_TEMPER;
                    *p1 = mk1 ? NEG_INF : (accv[i][1] + *p1) * INV_TEMPER;
                }
            } else {
                const unsigned char* mbase = (const unsigned char*)gmask + ((size_t)b*L_ + l0)*L_;
                #pragma unroll
                for (int i = 0; i < 16; ++i) {
                    const unsigned char mk0 = mbase[(size_t)i*L_ + r0];
                    const unsigned char mk1 = mbase[(size_t)i*L_ + r1];
                    float* p0 = sL + i*SL_STRIDE + r0;
                    float* p1 = sL + i*SL_STRIDE + r1;
                    *p0 = mk0 ? NEG_INF : (accv[i][0] + *p0) * INV_TEMPER;
                    *p1 = mk1 ? NEG_INF : (accv[i][1] + *p1) * INV_TEMPER;
                }
            }
            __syncthreads();
        }
    }

    // ================== Phase 3: softmax (one warp per row) + attn writeback ==========
    {
        const int row  = tid >> 5;     // 16 warps -> 16 rows
        const int lane = tid & 31;
        float* rowp = sL + row*SL_STRIDE;

        float mx = NEG_INF;
        #pragma unroll
        for (int j = 0; j < 8; ++j) {
            const float4 vv = *(const float4*)(rowp + j*128 + lane*4);
            mx = fmaxf(mx, fmaxf(fmaxf(vv.x, vv.y), fmaxf(vv.z, vv.w)));
        }
        #pragma unroll
        for (int o = 16; o; o >>= 1) mx = fmaxf(mx, __shfl_xor_sync(0xffffffffu, mx, o));

        float sum = 0.f;
        #pragma unroll
        for (int j = 0; j < 8; ++j) {
            float4 vv = *(float4*)(rowp + j*128 + lane*4);
            vv.x = __expf(vv.x - mx); vv.y = __expf(vv.y - mx);
            vv.z = __expf(vv.z - mx); vv.w = __expf(vv.w - mx);
            sum += (vv.x + vv.y) + (vv.z + vv.w);
            *(float4*)(rowp + j*128 + lane*4) = vv;   // unnormalized exp kept in sL
        }
        #pragma unroll
        for (int o = 16; o; o >>= 1) sum += __shfl_xor_sync(0xffffffffu, sum, o);
        const float inv = 1.f / sum;
        if (lane == 0) sInv[row] = inv;

        float* arow = gattn + ((size_t)b*L_ + (l0 + row))*L_;
        #pragma unroll
        for (int j = 0; j < 8; ++j) {
            float4 vv = *(const float4*)(rowp + j*128 + lane*4);
            vv.x *= inv; vv.y *= inv; vv.z *= inv; vv.w *= inv;
            *(float4*)(arow + j*128 + lane*4) = vv;
        }
    }
    __syncthreads();

    // ================== Phase 4: output = (exp-probs @ V) * inv =====================
    {
        const int cg = tid & 15;          // d-cols 4cg..4cg+3
        const int rg = (tid >> 4) & 3;    // rows 4rg..4rg+3
        const int ms = tid >> 6;          // 8 m-splits of 128

        // accp2[i][h]: row rg*4+i, h=0 -> d-cols (4cg,4cg+1), h=1 -> (4cg+2,4cg+3)
        unsigned long long accp2[4][2];
        #pragma unroll
        for (int i = 0; i < 4; ++i) { accp2[i][0] = 0ull; accp2[i][1] = 0ull; }

        const float* vbase = gv + ((size_t)b*L_ + ms*128)*DK_ + cg*4;
        const float* pbase = sL + (rg*4)*SL_STRIDE + ms*128;

        #pragma unroll 4
        for (int mm = 0; mm < 128; mm += 2) {
            const float4 v0 = *(const float4*)(vbase + (size_t)mm*DK_);
            const float4 v1 = *(const float4*)(vbase + (size_t)(mm+1)*DK_);
            const unsigned long long v0a = pack2(v0.x, v0.y), v0b = pack2(v0.z, v0.w);
            const unsigned long long v1a = pack2(v1.x, v1.y), v1b = pack2(v1.z, v1.w);
            #pragma unroll
            for (int i = 0; i < 4; ++i) {
                const float2 p = *(const float2*)(pbase + i*SL_STRIDE + mm);
                const unsigned long long pp0 = splat2(p.x);
                const unsigned long long pp1 = splat2(p.y);
                accp2[i][0] = fma2(pp0, v0a, accp2[i][0]);
                accp2[i][0] = fma2(pp1, v1a, accp2[i][0]);
                accp2[i][1] = fma2(pp0, v0b, accp2[i][1]);
                accp2[i][1] = fma2(pp1, v1b, accp2[i][1]);
            }
        }
        // partials: sCK[(ms*16 + row)*16 + cg] as float4
        #pragma unroll
        for (int i = 0; i < 4; ++i) {
            const float2 lo = unpack2(accp2[i][0]);
            const float2 hi = unpack2(accp2[i][1]);
            *(float4*)(sCK + (size_t)((ms*16 + rg*4 + i)*16 + cg)*4) =
                make_float4(lo.x, lo.y, hi.x, hi.y);
        }
    }
    __syncthreads();

    if (tid < 256) {
        const int row = tid >> 4, cg = tid & 15;
        float4 s = make_float4(0.f,0.f,0.f,0.f);
        #pragma unroll
        for (int ms = 0; ms < 8; ++ms) {
            const float4 p = *(const float4*)(sCK + (size_t)((ms*16 + row)*16 + cg)*4);
            s.x += p.x; s.y += p.y; s.z += p.z; s.w += p.w;
        }
        const float inv = sInv[row];
        s.x *= inv; s.y *= inv; s.z *= inv; s.w *= inv;
        *(float4*)(gout + ((size_t)b*L_ + (l0 + row))*DK_ + cg*4) = s;
    }
}

extern "C" void kernel_launch(void* const* d_in, const int* in_sizes, int n_in,
                              void* d_out, int out_size)
{
    // Identify inputs by element count; q,k,v in encounter order.
    const float* q   = nullptr;
    const float* k   = nullptr;
    const float* v   = nullptr;
    const float* pos = nullptr;
    const void*  mask = nullptr;
    int qkv_seen = 0;
    for (int i = 0; i < n_in; ++i) {
        const long long sz = in_sizes[i];
        if (sz == (long long)B_ * P_ * DK_) {
            pos = (const float*)d_in[i];
        } else if (sz == (long long)B_ * L_ * L_) {
            mask = d_in[i];
        } else if (sz == (long long)B_ * L_ * DK_) {
            if      (qkv_seen == 0) q = (const float*)d_in[i];
            else if (qkv_seen == 1) k = (const float*)d_in[i];
            else                    v = (const float*)d_in[i];
            ++qkv_seen;
        }
    }

    float* out  = (float*)d_out;                       // (B, L, DK) first
    float* attn = out + (size_t)B_ * L_ * DK_;         // (B, L, L) second

    cudaFuncSetAttribute(attn_fused_kernel,
                         cudaFuncAttributeMaxDynamicSharedMemorySize, SMEM_BYTES);

    detect_mask_kernel<<<1, 256>>>((const unsigned char*)mask);

    dim3 grid(L_ / TILE_L, B_);
    attn_fused_kernel<<<grid, NTHREADS, SMEM_BYTES>>>(q, k, v, pos, mask, out, attn);
}